// round 7
// baseline (speedup 1.0000x reference)
#include <cuda_runtime.h>
#include <math.h>
#include <stdint.h>

#define B_    4
#define T_    1000
#define C_    1024
#define H_    16
#define D_    64
#define M_TOK (B_*T_)   // 4000

// Scratch (allocation-free: device globals)
__device__ float g_q[B_*H_*T_*D_];
__device__ float g_k[B_*H_*T_*D_];
__device__ float g_v[B_*H_*T_*D_];
__device__ float g_y[M_TOK*C_];
__device__ float g_cos[T_*(D_/2)];
__device__ float g_sin[T_*(D_/2)];

// ---------------------------------------------------------------------------
__device__ __forceinline__ uint32_t f2tf32(float x) {
    uint32_t u;
    asm("cvt.rna.tf32.f32 %0, %1;" : "=r"(u) : "f"(x));
    return u;
}

__device__ __forceinline__ void mma_tf32(float c[4],
                                         const uint32_t a[4],
                                         const uint32_t b[2]) {
    asm volatile(
        "mma.sync.aligned.m16n8k8.row.col.f32.tf32.tf32.f32 "
        "{%0,%1,%2,%3}, {%4,%5,%6,%7}, {%8,%9}, {%0,%1,%2,%3};"
        : "+f"(c[0]), "+f"(c[1]), "+f"(c[2]), "+f"(c[3])
        : "r"(a[0]), "r"(a[1]), "r"(a[2]), "r"(a[3]),
          "r"(b[0]), "r"(b[1]));
}

// ---------------------------------------------------------------------------
__global__ void rope_table_kernel() {
    int t = blockIdx.x;
    int i = threadIdx.x;
    float theta = (float)pow(10000.0, -(double)(2 * i) / 64.0);
    float ang = (float)t * theta;
    g_cos[t * 32 + i] = cosf(ang);
    g_sin[t * 32 + i] = sinf(ang);
}

// ---------------------------------------------------------------------------
// 128x128 tf32 GEMM, double-buffered, fragment-ordered smem:
//  A frags stored as uint4 per (mb, s, lane): one LDS.128 feeds a whole
//  m16n8k8 A operand.  B frags stored as uint2 per (nb, s, lane): LDS.64.
//  A layout:  word = ((mb*2+s)*32 + tg*8 + g)*4 + (half + 2*chalf)
//  B layout:  word = ((nb*2+s)*32 + tg*8 + ((g+nb)&7))*2 + comp
// MODE 0: C = x @ W_attn, RoPE epilogue -> g_q/g_k/g_v.  MODE 1: -> Cout.
// ---------------------------------------------------------------------------
#define BK 16

template<int MODE>
__global__ void __launch_bounds__(256, 2)
gemm_tc(const float* __restrict__ Ain, const float* __restrict__ Bw,
        float* __restrict__ Cout, int M, int N, int K)
{
    const float* A = (MODE == 1) ? (const float*)g_y : Ain;

    __shared__ uint32_t As[2][2048];   // 8 mb * 2 s * 32 lanes * uint4
    __shared__ uint32_t Bs[2][2048];   // 16 nb * 2 s * 32 lanes * uint2

    const int tid  = threadIdx.x;
    const int warp = tid >> 5;
    const int lane = tid & 31;
    const int g    = lane >> 2;
    const int tg   = lane & 3;
    const int wm   = warp >> 2;
    const int wn   = warp & 3;
    const int wmB  = wm * 64;
    const int wnB  = wn * 32;

    const int bm = blockIdx.y * 128;
    const int bn = blockIdx.x * 128;

    float acc[4][4][4];
#pragma unroll
    for (int mf = 0; mf < 4; mf++)
#pragma unroll
        for (int nf = 0; nf < 4; nf++)
#pragma unroll
            for (int i = 0; i < 4; i++) acc[mf][nf][i] = 0.f;

    // ---- writer indexing ----
    // A: row = tid>>1, quads at cols q0=(tid&1)*8 and q0+4
    const int arow  = tid >> 1;
    const int Amb   = arow >> 4;
    const int Ag    = arow & 7;
    const int Ahalf = (arow >> 3) & 1;
    const int As_   = tid & 1;                 // k-step of this thread's quads
    const int q0    = As_ * 8;
    const int baseA0 = (Amb * 2 + As_) * 128 + Ag * 4 + Ahalf;       // chalf=0
    const int baseA1 = baseA0 + 2;                                   // chalf=1
    const bool arow_ok = (bm + arow < M);

    // B: row = tid>>4, cols nb*8 .. nb*8+7 with nb = tid&15
    const int brow  = tid >> 4;
    const int nbW   = tid & 15;
    const int baseB = ((nbW * 2 + (brow >> 3)) * 32 + (brow & 3) * 8) * 2
                    + ((brow >> 2) & 1);

    // ---- reader indexing (per-lane constants) ----
    const int laneA = (tg * 8 + g) * 4;

    float4 pa0, pa1, pb0, pb1;

    // prologue: load + store chunk 0 into stage 0
    {
        pa0 = make_float4(0.f, 0.f, 0.f, 0.f);
        pa1 = pa0;
        if (arow_ok) {
            pa0 = *(const float4*)(A + (size_t)(bm + arow) * K + q0);
            pa1 = *(const float4*)(A + (size_t)(bm + arow) * K + q0 + 4);
        }
        pb0 = *(const float4*)(Bw + (size_t)brow * N + bn + nbW * 8);
        pb1 = *(const float4*)(Bw + (size_t)brow * N + bn + nbW * 8 + 4);

        As[0][baseA0 +  0] = f2tf32(pa0.x);
        As[0][baseA0 + 32] = f2tf32(pa0.y);
        As[0][baseA0 + 64] = f2tf32(pa0.z);
        As[0][baseA0 + 96] = f2tf32(pa0.w);
        As[0][baseA1 +  0] = f2tf32(pa1.x);
        As[0][baseA1 + 32] = f2tf32(pa1.y);
        As[0][baseA1 + 64] = f2tf32(pa1.z);
        As[0][baseA1 + 96] = f2tf32(pa1.w);
        Bs[0][baseB + (((0 + nbW) & 7) << 1)] = f2tf32(pb0.x);
        Bs[0][baseB + (((1 + nbW) & 7) << 1)] = f2tf32(pb0.y);
        Bs[0][baseB + (((2 + nbW) & 7) << 1)] = f2tf32(pb0.z);
        Bs[0][baseB + (((3 + nbW) & 7) << 1)] = f2tf32(pb0.w);
        Bs[0][baseB + (((4 + nbW) & 7) << 1)] = f2tf32(pb1.x);
        Bs[0][baseB + (((5 + nbW) & 7) << 1)] = f2tf32(pb1.y);
        Bs[0][baseB + (((6 + nbW) & 7) << 1)] = f2tf32(pb1.z);
        Bs[0][baseB + (((7 + nbW) & 7) << 1)] = f2tf32(pb1.w);
    }
    __syncthreads();

    const int nchunk = K / BK;
    for (int ch = 0; ch < nchunk; ch++) {
        const int cur = ch & 1;
        const int nxt = cur ^ 1;
        const bool have_next = (ch + 1 < nchunk);

        if (have_next) {
            const int k0 = (ch + 1) * BK;
            pa0 = make_float4(0.f, 0.f, 0.f, 0.f);
            pa1 = pa0;
            if (arow_ok) {
                pa0 = *(const float4*)(A + (size_t)(bm + arow) * K + k0 + q0);
                pa1 = *(const float4*)(A + (size_t)(bm + arow) * K + k0 + q0 + 4);
            }
            pb0 = *(const float4*)(Bw + (size_t)(k0 + brow) * N + bn + nbW * 8);
            pb1 = *(const float4*)(Bw + (size_t)(k0 + brow) * N + bn + nbW * 8 + 4);
        }

        // compute current stage: 2 k-steps of 8
#pragma unroll
        for (int s = 0; s < 2; s++) {
            uint32_t afr[4][4], bfr[4][2];
#pragma unroll
            for (int mf = 0; mf < 4; mf++) {
                uint4 av = *(const uint4*)
                    &As[cur][((wm * 4 + mf) * 2 + s) * 128 + laneA];
                afr[mf][0] = av.x; afr[mf][1] = av.y;
                afr[mf][2] = av.z; afr[mf][3] = av.w;
            }
#pragma unroll
            for (int nf = 0; nf < 4; nf++) {
                int nb = wn * 4 + nf;
                uint2 bv = *(const uint2*)
                    &Bs[cur][((nb * 2 + s) * 32 + tg * 8 + ((g + nb) & 7)) * 2];
                bfr[nf][0] = bv.x; bfr[nf][1] = bv.y;
            }
#pragma unroll
            for (int mf = 0; mf < 4; mf++)
#pragma unroll
                for (int nf = 0; nf < 4; nf++)
                    mma_tf32(acc[mf][nf], afr[mf], bfr[nf]);
        }

        if (have_next) {
            As[nxt][baseA0 +  0] = f2tf32(pa0.x);
            As[nxt][baseA0 + 32] = f2tf32(pa0.y);
            As[nxt][baseA0 + 64] = f2tf32(pa0.z);
            As[nxt][baseA0 + 96] = f2tf32(pa0.w);
            As[nxt][baseA1 +  0] = f2tf32(pa1.x);
            As[nxt][baseA1 + 32] = f2tf32(pa1.y);
            As[nxt][baseA1 + 64] = f2tf32(pa1.z);
            As[nxt][baseA1 + 96] = f2tf32(pa1.w);
            Bs[nxt][baseB + (((0 + nbW) & 7) << 1)] = f2tf32(pb0.x);
            Bs[nxt][baseB + (((1 + nbW) & 7) << 1)] = f2tf32(pb0.y);
            Bs[nxt][baseB + (((2 + nbW) & 7) << 1)] = f2tf32(pb0.z);
            Bs[nxt][baseB + (((3 + nbW) & 7) << 1)] = f2tf32(pb0.w);
            Bs[nxt][baseB + (((4 + nbW) & 7) << 1)] = f2tf32(pb1.x);
            Bs[nxt][baseB + (((5 + nbW) & 7) << 1)] = f2tf32(pb1.y);
            Bs[nxt][baseB + (((6 + nbW) & 7) << 1)] = f2tf32(pb1.z);
            Bs[nxt][baseB + (((7 + nbW) & 7) << 1)] = f2tf32(pb1.w);
            __syncthreads();
        }
    }

    // ---------------- epilogue ----------------
    if (MODE == 1) {
#pragma unroll
        for (int mf = 0; mf < 4; mf++) {
#pragma unroll
            for (int half = 0; half < 2; half++) {
                int gr = bm + wmB + mf * 16 + g + half * 8;
                if (gr >= M) continue;
#pragma unroll
                for (int nf = 0; nf < 4; nf++) {
                    int c = bn + wnB + nf * 8 + tg * 2;
                    *(float2*)&Cout[(size_t)gr * N + c] =
                        make_float2(acc[mf][nf][2 * half], acc[mf][nf][2 * half + 1]);
                }
            }
        }
    } else {
        int cwarp = bn + wnB;
        int which = cwarp >> 10;
        int h     = (cwarp & 1023) >> 6;
#pragma unroll
        for (int mf = 0; mf < 4; mf++) {
#pragma unroll
            for (int half = 0; half < 2; half++) {
                int gr = bm + wmB + mf * 16 + g + half * 8;
                if (gr >= M) continue;
                int b = gr / T_;
                int t = gr - b * T_;
                size_t rowbase = ((size_t)(b * H_ + h) * T_ + t) * D_;
#pragma unroll
                for (int nf = 0; nf < 4; nf++) {
                    int c     = bn + wnB + nf * 8 + tg * 2;
                    int dbase = c & 63;
                    float x0 = acc[mf][nf][2 * half];
                    float x1 = acc[mf][nf][2 * half + 1];
                    if (which == 2) {
                        *(float2*)&g_v[rowbase + dbase] = make_float2(x0, x1);
                    } else {
                        int pi = dbase >> 1;
                        float ct = g_cos[t * 32 + pi];
                        float st = g_sin[t * 32 + pi];
                        float* dst = (which == 0 ? g_q : g_k) + rowbase + dbase;
                        *(float2*)dst = make_float2(x0 * ct - x1 * st,
                                                    x1 * ct + x0 * st);
                    }
                }
            }
        }
    }
}

// ---------------------------------------------------------------------------
// Tensor-core flash attention (tf32 mma) — unchanged from R6 (known good).
// ---------------------------------------------------------------------------
#define AP 68   // smem row pad (words)

__global__ void __launch_bounds__(128) attn_tc_kernel() {
    const int qt = (int)gridDim.x - 1 - (int)blockIdx.x;  // heavy tiles first
    const int h  = blockIdx.y;
    const int b  = blockIdx.z;

    __shared__ uint32_t SmA[64 * AP];   // K tile, then P tile (and Q staging)
    __shared__ uint32_t SmV[64 * AP];   // V tile

    const int tid  = threadIdx.x;
    const int warp = tid >> 5;
    const int lane = tid & 31;
    const int g    = lane >> 2;
    const int tg   = lane & 3;
    const int qw   = warp * 16;

    const size_t base = (size_t)(b * H_ + h) * T_ * D_;

    // ---- stage Q tile, extract Q^T B-fragments into registers ----
    float* Qs = (float*)SmA;
#pragma unroll
    for (int u = 0; u < 8; u++) {
        int i  = u * 128 + tid;
        int q  = i >> 4;
        int d4 = (i & 15) * 4;
        int row = min(qt * 64 + q, T_ - 1);
        *(float4*)&Qs[q * AP + d4] = *(const float4*)&g_q[base + (size_t)row * D_ + d4];
    }
    __syncthreads();

    uint32_t qb[8][2][2];
#pragma unroll
    for (int s = 0; s < 8; s++)
#pragma unroll
        for (int nf = 0; nf < 2; nf++) {
            int col = qw + nf * 8 + g;
            qb[s][nf][0] = f2tf32(Qs[col * AP + 8 * s + tg] * 0.125f);
            qb[s][nf][1] = f2tf32(Qs[col * AP + 8 * s + tg + 4] * 0.125f);
        }
    __syncthreads();

    // ---- persistent state ----
    float Ofr[8][4];
#pragma unroll
    for (int nf = 0; nf < 8; nf++)
#pragma unroll
        for (int i = 0; i < 4; i++) Ofr[nf][i] = 0.f;
    float mrun[4] = {-1e30f, -1e30f, -1e30f, -1e30f};
    float lrun[4] = {0.f, 0.f, 0.f, 0.f};

    const int srcl = (g >> 1) & 3;   // shfl source for col->row exchange

    for (int kt = 0; kt <= qt; kt++) {
        const int kb = kt * 64;

#pragma unroll
        for (int u = 0; u < 8; u++) {
            int i  = u * 128 + tid;
            int kv = i >> 4;
            int d4 = (i & 15) * 4;
            int row = min(kb + kv, T_ - 1);
            float4 kk = *(const float4*)&g_k[base + (size_t)row * D_ + d4];
            float4 vv = *(const float4*)&g_v[base + (size_t)row * D_ + d4];
            *(uint4*)&SmA[kv * AP + d4] =
                make_uint4(f2tf32(kk.x), f2tf32(kk.y), f2tf32(kk.z), f2tf32(kk.w));
            *(uint4*)&SmV[kv * AP + d4] =
                make_uint4(f2tf32(vv.x), f2tf32(vv.y), f2tf32(vv.z), f2tf32(vv.w));
        }
        __syncthreads();

        // ---- Phase A: S^T[kv][q] = K · Q^T ----
        float cS[4][2][4];
#pragma unroll
        for (int mf = 0; mf < 4; mf++)
#pragma unroll
            for (int nf = 0; nf < 2; nf++)
#pragma unroll
                for (int i = 0; i < 4; i++) cS[mf][nf][i] = 0.f;

#pragma unroll
        for (int s = 0; s < 8; s++) {
#pragma unroll
            for (int mf = 0; mf < 4; mf++) {
                uint32_t a[4];
                a[0] = SmA[(mf * 16 + g)     * AP + 8 * s + tg];
                a[1] = SmA[(mf * 16 + g + 8) * AP + 8 * s + tg];
                a[2] = SmA[(mf * 16 + g)     * AP + 8 * s + tg + 4];
                a[3] = SmA[(mf * 16 + g + 8) * AP + 8 * s + tg + 4];
                mma_tf32(cS[mf][0], a, qb[s][0]);
                mma_tf32(cS[mf][1], a, qb[s][1]);
            }
        }

        // causal mask (only the diagonal tile has masked entries)
        if (kt == qt) {
#pragma unroll
            for (int mf = 0; mf < 4; mf++)
#pragma unroll
                for (int nf = 0; nf < 2; nf++)
#pragma unroll
                    for (int i = 0; i < 4; i++) {
                        int kvg = kb + mf * 16 + g + (i >> 1) * 8;
                        int qg  = qt * 64 + qw + nf * 8 + 2 * tg + (i & 1);
                        if (kvg > qg) cS[mf][nf][i] = -1e30f;
                    }
        }

        // ---- softmax over q-columns ----
        float tmax[4];
#pragma unroll
        for (int nf = 0; nf < 2; nf++)
#pragma unroll
            for (int e = 0; e < 2; e++) {
                float v = -1e30f;
#pragma unroll
                for (int mf = 0; mf < 4; mf++)
                    v = fmaxf(v, fmaxf(cS[mf][nf][e], cS[mf][nf][2 + e]));
                tmax[nf * 2 + e] = v;
            }
#pragma unroll
        for (int st = 0; st < 4; st++) {
            tmax[st] = fmaxf(tmax[st], __shfl_xor_sync(0xffffffffu, tmax[st], 4));
            tmax[st] = fmaxf(tmax[st], __shfl_xor_sync(0xffffffffu, tmax[st], 8));
            tmax[st] = fmaxf(tmax[st], __shfl_xor_sync(0xffffffffu, tmax[st], 16));
        }
        float fst[4];
#pragma unroll
        for (int st = 0; st < 4; st++) {
            float mnew = fmaxf(mrun[st], tmax[st]);
            fst[st] = __expf(mrun[st] - mnew);
            mrun[st] = mnew;
            lrun[st] *= fst[st];
        }

        // P = exp(S - m), accumulate l partials (per-thread; g-reduced at end)
#pragma unroll
        for (int mf = 0; mf < 4; mf++)
#pragma unroll
            for (int nf = 0; nf < 2; nf++)
#pragma unroll
                for (int i = 0; i < 4; i++) {
                    float p = __expf(cS[mf][nf][i] - mrun[nf * 2 + (i & 1)]);
                    cS[mf][nf][i] = p;
                    lrun[nf * 2 + (i & 1)] += p;
                }

        __syncthreads();   // all warps done reading K tile (SmA) in phase A

        // store P^T -> Ps[q][kv]  (scatter: bank = 8*tg+g, conflict-free)
        uint32_t* Ps = SmA;
#pragma unroll
        for (int mf = 0; mf < 4; mf++)
#pragma unroll
            for (int nf = 0; nf < 2; nf++)
#pragma unroll
                for (int i = 0; i < 4; i++) {
                    int qloc = qw + nf * 8 + 2 * tg + (i & 1);
                    int kv   = mf * 16 + g + (i >> 1) * 8;
                    Ps[qloc * AP + kv] = f2tf32(cS[mf][nf][i]);
                }
        __syncwarp();

        // rescale O by f (exchange col-state -> row-state, 4 shfls)
        {
            float f0 = __shfl_sync(0xffffffffu, fst[0], srcl);
            float f1 = __shfl_sync(0xffffffffu, fst[1], srcl);
            float f2 = __shfl_sync(0xffffffffu, fst[2], srcl);
            float f3 = __shfl_sync(0xffffffffu, fst[3], srcl);
            float fr0 = (g & 1) ? f1 : f0;
            float fr1 = (g & 1) ? f3 : f2;
#pragma unroll
            for (int nf = 0; nf < 8; nf++) {
                Ofr[nf][0] *= fr0;
                Ofr[nf][1] *= fr0;
                Ofr[nf][2] *= fr1;
                Ofr[nf][3] *= fr1;
            }
        }

        // ---- Phase B: O[q][d] += P · V ----
#pragma unroll
        for (int s = 0; s < 8; s++) {
            uint32_t a[4];
            a[0] = Ps[(qw + g)     * AP + 8 * s + tg];
            a[1] = Ps[(qw + g + 8) * AP + 8 * s + tg];
            a[2] = Ps[(qw + g)     * AP + 8 * s + tg + 4];
            a[3] = Ps[(qw + g + 8) * AP + 8 * s + tg + 4];
#pragma unroll
            for (int nf = 0; nf < 8; nf++) {
                uint32_t bb[2];
                bb[0] = SmV[(8 * s + tg)     * AP + nf * 8 + g];
                bb[1] = SmV[(8 * s + tg + 4) * AP + nf * 8 + g];
                mma_tf32(Ofr[nf], a, bb);
            }
        }
        __syncthreads();   // before next tile overwrites SmA/SmV
    }

    // reduce l partials across the 8 g-lanes of each q-column
#pragma unroll
    for (int st = 0; st < 4; st++) {
        lrun[st] += __shfl_xor_sync(0xffffffffu, lrun[st], 4);
        lrun[st] += __shfl_xor_sync(0xffffffffu, lrun[st], 8);
        lrun[st] += __shfl_xor_sync(0xffffffffu, lrun[st], 16);
    }

    // ---- final: exchange l to row ownership, normalize, write ----
    float l0 = __shfl_sync(0xffffffffu, lrun[0], srcl);
    float l1 = __shfl_sync(0xffffffffu, lrun[1], srcl);
    float l2 = __shfl_sync(0xffffffffu, lrun[2], srcl);
    float l3 = __shfl_sync(0xffffffffu, lrun[3], srcl);
    float lr0 = (g & 1) ? l1 : l0;
    float lr1 = (g & 1) ? l3 : l2;
    float inv0 = 1.f / lr0;
    float inv1 = 1.f / lr1;

    int qg0 = qt * 64 + qw + g;
    int qg1 = qg0 + 8;
    if (qg0 < T_) {
        float* yp = &g_y[((size_t)(b * T_) + qg0) * C_ + h * D_];
#pragma unroll
        for (int nf = 0; nf < 8; nf++)
            *(float2*)&yp[nf * 8 + 2 * tg] =
                make_float2(Ofr[nf][0] * inv0, Ofr[nf][1] * inv0);
    }
    if (qg1 < T_) {
        float* yp = &g_y[((size_t)(b * T_) + qg1) * C_ + h * D_];
#pragma unroll
        for (int nf = 0; nf < 8; nf++)
            *(float2*)&yp[nf * 8 + 2 * tg] =
                make_float2(Ofr[nf][2] * inv1, Ofr[nf][3] * inv1);
    }
}

// ---------------------------------------------------------------------------
extern "C" void kernel_launch(void* const* d_in, const int* in_sizes, int n_in,
                              void* d_out, int out_size)
{
    const float* x      = (const float*)d_in[0];
    const float* W_attn = (const float*)d_in[2];
    const float* W_proj = (const float*)d_in[3];
    float* out = (float*)d_out;

    rope_table_kernel<<<T_, 32>>>();

    dim3 g_qkv(3072 / 128, (M_TOK + 127) / 128);   // 24 x 32
    gemm_tc<0><<<g_qkv, 256>>>(x, W_attn, nullptr, M_TOK, 3072, 1024);

    dim3 g_attn((T_ + 63) / 64, H_, B_);           // 16 x 16 x 4
    attn_tc_kernel<<<g_attn, 128>>>();

    dim3 g_proj(1024 / 128, (M_TOK + 127) / 128);  // 8 x 32
    gemm_tc<1><<<g_proj, 256>>>(nullptr, W_proj, out, M_TOK, 1024, 1024);
}

// round 8
// speedup vs baseline: 1.5228x; 1.5228x over previous
#include <cuda_runtime.h>
#include <math.h>
#include <stdint.h>

#define B_    4
#define T_    1000
#define C_    1024
#define H_    16
#define D_    64
#define M_TOK (B_*T_)   // 4000

// Scratch (allocation-free: device globals)
__device__ float g_q[B_*H_*T_*D_];
__device__ float g_k[B_*H_*T_*D_];
__device__ float g_v[B_*H_*T_*D_];
__device__ float g_y[M_TOK*C_];
__device__ float g_cos[T_*(D_/2)];
__device__ float g_sin[T_*(D_/2)];

// ---------------------------------------------------------------------------
__device__ __forceinline__ uint32_t f2tf32(float x) {
    uint32_t u;
    asm("cvt.rna.tf32.f32 %0, %1;" : "=r"(u) : "f"(x));
    return u;
}

__device__ __forceinline__ void mma_tf32(float c[4],
                                         const uint32_t a[4],
                                         const uint32_t b[2]) {
    asm volatile(
        "mma.sync.aligned.m16n8k8.row.col.f32.tf32.tf32.f32 "
        "{%0,%1,%2,%3}, {%4,%5,%6,%7}, {%8,%9}, {%0,%1,%2,%3};"
        : "+f"(c[0]), "+f"(c[1]), "+f"(c[2]), "+f"(c[3])
        : "r"(a[0]), "r"(a[1]), "r"(a[2]), "r"(a[3]),
          "r"(b[0]), "r"(b[1]));
}

__device__ __forceinline__ void ldsm_x4(uint32_t r[4], uint32_t smaddr) {
    asm volatile(
        "ldmatrix.sync.aligned.m8n8.x4.shared.b16 {%0,%1,%2,%3}, [%4];"
        : "=r"(r[0]), "=r"(r[1]), "=r"(r[2]), "=r"(r[3])
        : "r"(smaddr));
}

// ---------------------------------------------------------------------------
__global__ void rope_table_kernel() {
    int t = blockIdx.x;
    int i = threadIdx.x;
    float theta = (float)pow(10000.0, -(double)(2 * i) / 64.0);
    float ang = (float)t * theta;
    g_cos[t * 32 + i] = cosf(ang);
    g_sin[t * 32 + i] = sinf(ang);
}

// ---------------------------------------------------------------------------
// 128x128 tf32 GEMM, double-buffered, A fragments via ldmatrix.x4.
//  A smem: [m=128][k=16] u32, row stride AST=20 (LDSM conflict-free, 16B rows)
//  B smem: [k=16][n=128] u32, row stride LDS_=136 (R6 layout, conflict-free)
// MODE 0: C = x @ W_attn, RoPE epilogue -> g_q/g_k/g_v.  MODE 1: -> Cout.
// ---------------------------------------------------------------------------
#define BK   16
#define AST  20
#define LDS_ 136

template<int MODE>
__global__ void __launch_bounds__(256, 2)
gemm_tc(const float* __restrict__ Ain, const float* __restrict__ Bw,
        float* __restrict__ Cout, int M, int N, int K)
{
    const float* A = (MODE == 1) ? (const float*)g_y : Ain;

    __shared__ __align__(16) uint32_t As[2][128 * AST];
    __shared__ uint32_t Bs[2][BK * LDS_];

    const int tid  = threadIdx.x;
    const int warp = tid >> 5;
    const int lane = tid & 31;
    const int g    = lane >> 2;
    const int tg   = lane & 3;
    const int wm   = warp >> 2;
    const int wn   = warp & 3;
    const int wmB  = wm * 64;
    const int wnB  = wn * 32;

    const int bm = blockIdx.y * 128;
    const int bn = blockIdx.x * 128;

    float acc[4][4][4];
#pragma unroll
    for (int mf = 0; mf < 4; mf++)
#pragma unroll
        for (int nf = 0; nf < 4; nf++)
#pragma unroll
            for (int i = 0; i < 4; i++) acc[mf][nf][i] = 0.f;

    // ---- writer indexing ----
    const int arow = tid >> 1;           // 0..127
    const int q0   = (tid & 1) * 8;      // 0 or 8
    const bool arow_ok = (bm + arow < M);
    const int brow = tid >> 4;           // 0..15
    const int bc0  = (tid & 15) * 8;     // 0..120

    // ---- LDSM lane addressing (A reader) ----
    const int rA = (lane & 7) + ((lane >> 3) & 1) * 8;  // row within 16-row frag
    const int cA = (lane >> 4) * 4;                     // k-half within 8

    float4 pa0, pa1, pb0, pb1;

    // prologue: load chunk 0 + store into stage 0
    {
        pa0 = make_float4(0.f, 0.f, 0.f, 0.f);
        pa1 = pa0;
        if (arow_ok) {
            pa0 = *(const float4*)(A + (size_t)(bm + arow) * K + q0);
            pa1 = *(const float4*)(A + (size_t)(bm + arow) * K + q0 + 4);
        }
        pb0 = *(const float4*)(Bw + (size_t)brow * N + bn + bc0);
        pb1 = *(const float4*)(Bw + (size_t)brow * N + bn + bc0 + 4);

        *(uint4*)&As[0][arow * AST + q0] =
            make_uint4(f2tf32(pa0.x), f2tf32(pa0.y), f2tf32(pa0.z), f2tf32(pa0.w));
        *(uint4*)&As[0][arow * AST + q0 + 4] =
            make_uint4(f2tf32(pa1.x), f2tf32(pa1.y), f2tf32(pa1.z), f2tf32(pa1.w));
        *(uint4*)&Bs[0][brow * LDS_ + bc0] =
            make_uint4(f2tf32(pb0.x), f2tf32(pb0.y), f2tf32(pb0.z), f2tf32(pb0.w));
        *(uint4*)&Bs[0][brow * LDS_ + bc0 + 4] =
            make_uint4(f2tf32(pb1.x), f2tf32(pb1.y), f2tf32(pb1.z), f2tf32(pb1.w));
    }
    __syncthreads();

    const int nchunk = K / BK;
    for (int ch = 0; ch < nchunk; ch++) {
        const int cur = ch & 1;
        const int nxt = cur ^ 1;
        const bool have_next = (ch + 1 < nchunk);

        // issue next-chunk global loads first (latency hidden by compute)
        if (have_next) {
            const int k0 = (ch + 1) * BK;
            pa0 = make_float4(0.f, 0.f, 0.f, 0.f);
            pa1 = pa0;
            if (arow_ok) {
                pa0 = *(const float4*)(A + (size_t)(bm + arow) * K + k0 + q0);
                pa1 = *(const float4*)(A + (size_t)(bm + arow) * K + k0 + q0 + 4);
            }
            pb0 = *(const float4*)(Bw + (size_t)(k0 + brow) * N + bn + bc0);
            pb1 = *(const float4*)(Bw + (size_t)(k0 + brow) * N + bn + bc0 + 4);
        }

        const uint32_t asbase =
            (uint32_t)__cvta_generic_to_shared(&As[cur][0]);

        // compute current stage: 2 k-steps of 8
#pragma unroll
        for (int s = 0; s < 2; s++) {
            uint32_t afr[4][4], bfr[4][2];
#pragma unroll
            for (int mf = 0; mf < 4; mf++) {
                uint32_t addr = asbase +
                    (((wmB + mf * 16 + rA) * AST + 8 * s + cA) << 2);
                ldsm_x4(afr[mf], addr);
            }
            const int kr0 = (8 * s + tg) * LDS_;
            const int kr1 = (8 * s + tg + 4) * LDS_;
#pragma unroll
            for (int nf = 0; nf < 4; nf++) {
                int n0 = wnB + nf * 8 + g;
                bfr[nf][0] = Bs[cur][kr0 + n0];
                bfr[nf][1] = Bs[cur][kr1 + n0];
            }
#pragma unroll
            for (int mf = 0; mf < 4; mf++)
#pragma unroll
                for (int nf = 0; nf < 4; nf++)
                    mma_tf32(acc[mf][nf], afr[mf], bfr[nf]);
        }

        // store prefetched chunk into the other stage
        if (have_next) {
            *(uint4*)&As[nxt][arow * AST + q0] =
                make_uint4(f2tf32(pa0.x), f2tf32(pa0.y), f2tf32(pa0.z), f2tf32(pa0.w));
            *(uint4*)&As[nxt][arow * AST + q0 + 4] =
                make_uint4(f2tf32(pa1.x), f2tf32(pa1.y), f2tf32(pa1.z), f2tf32(pa1.w));
            *(uint4*)&Bs[nxt][brow * LDS_ + bc0] =
                make_uint4(f2tf32(pb0.x), f2tf32(pb0.y), f2tf32(pb0.z), f2tf32(pb0.w));
            *(uint4*)&Bs[nxt][brow * LDS_ + bc0 + 4] =
                make_uint4(f2tf32(pb1.x), f2tf32(pb1.y), f2tf32(pb1.z), f2tf32(pb1.w));
            __syncthreads();
        }
    }

    // ---------------- epilogue ----------------
    if (MODE == 1) {
#pragma unroll
        for (int mf = 0; mf < 4; mf++) {
#pragma unroll
            for (int half = 0; half < 2; half++) {
                int gr = bm + wmB + mf * 16 + g + half * 8;
                if (gr >= M) continue;
#pragma unroll
                for (int nf = 0; nf < 4; nf++) {
                    int c = bn + wnB + nf * 8 + tg * 2;
                    *(float2*)&Cout[(size_t)gr * N + c] =
                        make_float2(acc[mf][nf][2 * half], acc[mf][nf][2 * half + 1]);
                }
            }
        }
    } else {
        int cwarp = bn + wnB;
        int which = cwarp >> 10;
        int h     = (cwarp & 1023) >> 6;
#pragma unroll
        for (int mf = 0; mf < 4; mf++) {
#pragma unroll
            for (int half = 0; half < 2; half++) {
                int gr = bm + wmB + mf * 16 + g + half * 8;
                if (gr >= M) continue;
                int b = gr / T_;
                int t = gr - b * T_;
                size_t rowbase = ((size_t)(b * H_ + h) * T_ + t) * D_;
#pragma unroll
                for (int nf = 0; nf < 4; nf++) {
                    int c     = bn + wnB + nf * 8 + tg * 2;
                    int dbase = c & 63;
                    float x0 = acc[mf][nf][2 * half];
                    float x1 = acc[mf][nf][2 * half + 1];
                    if (which == 2) {
                        *(float2*)&g_v[rowbase + dbase] = make_float2(x0, x1);
                    } else {
                        int pi = dbase >> 1;
                        float ct = g_cos[t * 32 + pi];
                        float st = g_sin[t * 32 + pi];
                        float* dst = (which == 0 ? g_q : g_k) + rowbase + dbase;
                        *(float2*)dst = make_float2(x0 * ct - x1 * st,
                                                    x1 * ct + x0 * st);
                    }
                }
            }
        }
    }
}

// ---------------------------------------------------------------------------
// Tensor-core flash attention (tf32 mma) — unchanged from R6 (known good).
// ---------------------------------------------------------------------------
#define AP 68   // smem row pad (words)

__global__ void __launch_bounds__(128) attn_tc_kernel() {
    const int qt = (int)gridDim.x - 1 - (int)blockIdx.x;  // heavy tiles first
    const int h  = blockIdx.y;
    const int b  = blockIdx.z;

    __shared__ uint32_t SmA[64 * AP];   // K tile, then P tile (and Q staging)
    __shared__ uint32_t SmV[64 * AP];   // V tile

    const int tid  = threadIdx.x;
    const int warp = tid >> 5;
    const int lane = tid & 31;
    const int g    = lane >> 2;
    const int tg   = lane & 3;
    const int qw   = warp * 16;

    const size_t base = (size_t)(b * H_ + h) * T_ * D_;

    // ---- stage Q tile, extract Q^T B-fragments into registers ----
    float* Qs = (float*)SmA;
#pragma unroll
    for (int u = 0; u < 8; u++) {
        int i  = u * 128 + tid;
        int q  = i >> 4;
        int d4 = (i & 15) * 4;
        int row = min(qt * 64 + q, T_ - 1);
        *(float4*)&Qs[q * AP + d4] = *(const float4*)&g_q[base + (size_t)row * D_ + d4];
    }
    __syncthreads();

    uint32_t qb[8][2][2];
#pragma unroll
    for (int s = 0; s < 8; s++)
#pragma unroll
        for (int nf = 0; nf < 2; nf++) {
            int col = qw + nf * 8 + g;
            qb[s][nf][0] = f2tf32(Qs[col * AP + 8 * s + tg] * 0.125f);
            qb[s][nf][1] = f2tf32(Qs[col * AP + 8 * s + tg + 4] * 0.125f);
        }
    __syncthreads();

    // ---- persistent state ----
    float Ofr[8][4];
#pragma unroll
    for (int nf = 0; nf < 8; nf++)
#pragma unroll
        for (int i = 0; i < 4; i++) Ofr[nf][i] = 0.f;
    float mrun[4] = {-1e30f, -1e30f, -1e30f, -1e30f};
    float lrun[4] = {0.f, 0.f, 0.f, 0.f};

    const int srcl = (g >> 1) & 3;   // shfl source for col->row exchange

    for (int kt = 0; kt <= qt; kt++) {
        const int kb = kt * 64;

#pragma unroll
        for (int u = 0; u < 8; u++) {
            int i  = u * 128 + tid;
            int kv = i >> 4;
            int d4 = (i & 15) * 4;
            int row = min(kb + kv, T_ - 1);
            float4 kk = *(const float4*)&g_k[base + (size_t)row * D_ + d4];
            float4 vv = *(const float4*)&g_v[base + (size_t)row * D_ + d4];
            *(uint4*)&SmA[kv * AP + d4] =
                make_uint4(f2tf32(kk.x), f2tf32(kk.y), f2tf32(kk.z), f2tf32(kk.w));
            *(uint4*)&SmV[kv * AP + d4] =
                make_uint4(f2tf32(vv.x), f2tf32(vv.y), f2tf32(vv.z), f2tf32(vv.w));
        }
        __syncthreads();

        // ---- Phase A: S^T[kv][q] = K · Q^T ----
        float cS[4][2][4];
#pragma unroll
        for (int mf = 0; mf < 4; mf++)
#pragma unroll
            for (int nf = 0; nf < 2; nf++)
#pragma unroll
                for (int i = 0; i < 4; i++) cS[mf][nf][i] = 0.f;

#pragma unroll
        for (int s = 0; s < 8; s++) {
#pragma unroll
            for (int mf = 0; mf < 4; mf++) {
                uint32_t a[4];
                a[0] = SmA[(mf * 16 + g)     * AP + 8 * s + tg];
                a[1] = SmA[(mf * 16 + g + 8) * AP + 8 * s + tg];
                a[2] = SmA[(mf * 16 + g)     * AP + 8 * s + tg + 4];
                a[3] = SmA[(mf * 16 + g + 8) * AP + 8 * s + tg + 4];
                mma_tf32(cS[mf][0], a, qb[s][0]);
                mma_tf32(cS[mf][1], a, qb[s][1]);
            }
        }

        // causal mask (only the diagonal tile has masked entries)
        if (kt == qt) {
#pragma unroll
            for (int mf = 0; mf < 4; mf++)
#pragma unroll
                for (int nf = 0; nf < 2; nf++)
#pragma unroll
                    for (int i = 0; i < 4; i++) {
                        int kvg = kb + mf * 16 + g + (i >> 1) * 8;
                        int qg  = qt * 64 + qw + nf * 8 + 2 * tg + (i & 1);
                        if (kvg > qg) cS[mf][nf][i] = -1e30f;
                    }
        }

        // ---- softmax over q-columns ----
        float tmax[4];
#pragma unroll
        for (int nf = 0; nf < 2; nf++)
#pragma unroll
            for (int e = 0; e < 2; e++) {
                float v = -1e30f;
#pragma unroll
                for (int mf = 0; mf < 4; mf++)
                    v = fmaxf(v, fmaxf(cS[mf][nf][e], cS[mf][nf][2 + e]));
                tmax[nf * 2 + e] = v;
            }
#pragma unroll
        for (int st = 0; st < 4; st++) {
            tmax[st] = fmaxf(tmax[st], __shfl_xor_sync(0xffffffffu, tmax[st], 4));
            tmax[st] = fmaxf(tmax[st], __shfl_xor_sync(0xffffffffu, tmax[st], 8));
            tmax[st] = fmaxf(tmax[st], __shfl_xor_sync(0xffffffffu, tmax[st], 16));
        }
        float fst[4];
#pragma unroll
        for (int st = 0; st < 4; st++) {
            float mnew = fmaxf(mrun[st], tmax[st]);
            fst[st] = __expf(mrun[st] - mnew);
            mrun[st] = mnew;
            lrun[st] *= fst[st];
        }

        // P = exp(S - m), accumulate l partials (per-thread; g-reduced at end)
#pragma unroll
        for (int mf = 0; mf < 4; mf++)
#pragma unroll
            for (int nf = 0; nf < 2; nf++)
#pragma unroll
                for (int i = 0; i < 4; i++) {
                    float p = __expf(cS[mf][nf][i] - mrun[nf * 2 + (i & 1)]);
                    cS[mf][nf][i] = p;
                    lrun[nf * 2 + (i & 1)] += p;
                }

        __syncthreads();   // all warps done reading K tile (SmA) in phase A

        // store P^T -> Ps[q][kv]  (scatter: bank = 8*tg+g, conflict-free)
        uint32_t* Ps = SmA;
#pragma unroll
        for (int mf = 0; mf < 4; mf++)
#pragma unroll
            for (int nf = 0; nf < 2; nf++)
#pragma unroll
                for (int i = 0; i < 4; i++) {
                    int qloc = qw + nf * 8 + 2 * tg + (i & 1);
                    int kv   = mf * 16 + g + (i >> 1) * 8;
                    Ps[qloc * AP + kv] = f2tf32(cS[mf][nf][i]);
                }
        __syncwarp();

        // rescale O by f (exchange col-state -> row-state, 4 shfls)
        {
            float f0 = __shfl_sync(0xffffffffu, fst[0], srcl);
            float f1 = __shfl_sync(0xffffffffu, fst[1], srcl);
            float f2 = __shfl_sync(0xffffffffu, fst[2], srcl);
            float f3 = __shfl_sync(0xffffffffu, fst[3], srcl);
            float fr0 = (g & 1) ? f1 : f0;
            float fr1 = (g & 1) ? f3 : f2;
#pragma unroll
            for (int nf = 0; nf < 8; nf++) {
                Ofr[nf][0] *= fr0;
                Ofr[nf][1] *= fr0;
                Ofr[nf][2] *= fr1;
                Ofr[nf][3] *= fr1;
            }
        }

        // ---- Phase B: O[q][d] += P · V ----
#pragma unroll
        for (int s = 0; s < 8; s++) {
            uint32_t a[4];
            a[0] = Ps[(qw + g)     * AP + 8 * s + tg];
            a[1] = Ps[(qw + g + 8) * AP + 8 * s + tg];
            a[2] = Ps[(qw + g)     * AP + 8 * s + tg + 4];
            a[3] = Ps[(qw + g + 8) * AP + 8 * s + tg + 4];
#pragma unroll
            for (int nf = 0; nf < 8; nf++) {
                uint32_t bb[2];
                bb[0] = SmV[(8 * s + tg)     * AP + nf * 8 + g];
                bb[1] = SmV[(8 * s + tg + 4) * AP + nf * 8 + g];
                mma_tf32(Ofr[nf], a, bb);
            }
        }
        __syncthreads();   // before next tile overwrites SmA/SmV
    }

    // reduce l partials across the 8 g-lanes of each q-column
#pragma unroll
    for (int st = 0; st < 4; st++) {
        lrun[st] += __shfl_xor_sync(0xffffffffu, lrun[st], 4);
        lrun[st] += __shfl_xor_sync(0xffffffffu, lrun[st], 8);
        lrun[st] += __shfl_xor_sync(0xffffffffu, lrun[st], 16);
    }

    // ---- final: exchange l to row ownership, normalize, write ----
    float l0 = __shfl_sync(0xffffffffu, lrun[0], srcl);
    float l1 = __shfl_sync(0xffffffffu, lrun[1], srcl);
    float l2 = __shfl_sync(0xffffffffu, lrun[2], srcl);
    float l3 = __shfl_sync(0xffffffffu, lrun[3], srcl);
    float lr0 = (g & 1) ? l1 : l0;
    float lr1 = (g & 1) ? l3 : l2;
    float inv0 = 1.f / lr0;
    float inv1 = 1.f / lr1;

    int qg0 = qt * 64 + qw + g;
    int qg1 = qg0 + 8;
    if (qg0 < T_) {
        float* yp = &g_y[((size_t)(b * T_) + qg0) * C_ + h * D_];
#pragma unroll
        for (int nf = 0; nf < 8; nf++)
            *(float2*)&yp[nf * 8 + 2 * tg] =
                make_float2(Ofr[nf][0] * inv0, Ofr[nf][1] * inv0);
    }
    if (qg1 < T_) {
        float* yp = &g_y[((size_t)(b * T_) + qg1) * C_ + h * D_];
#pragma unroll
        for (int nf = 0; nf < 8; nf++)
            *(float2*)&yp[nf * 8 + 2 * tg] =
                make_float2(Ofr[nf][2] * inv1, Ofr[nf][3] * inv1);
    }
}

// ---------------------------------------------------------------------------
extern "C" void kernel_launch(void* const* d_in, const int* in_sizes, int n_in,
                              void* d_out, int out_size)
{
    const float* x      = (const float*)d_in[0];
    const float* W_attn = (const float*)d_in[2];
    const float* W_proj = (const float*)d_in[3];
    float* out = (float*)d_out;

    rope_table_kernel<<<T_, 32>>>();

    dim3 g_qkv(3072 / 128, (M_TOK + 127) / 128);   // 24 x 32
    gemm_tc<0><<<g_qkv, 256>>>(x, W_attn, nullptr, M_TOK, 3072, 1024);

    dim3 g_attn((T_ + 63) / 64, H_, B_);           // 16 x 16 x 4
    attn_tc_kernel<<<g_attn, 128>>>();

    dim3 g_proj(1024 / 128, (M_TOK + 127) / 128);  // 8 x 32
    gemm_tc<1><<<g_proj, 256>>>(nullptr, W_proj, out, M_TOK, 1024, 1024);
}